// round 16
// baseline (speedup 1.0000x reference)
#include <cuda_runtime.h>
#include <cuda_bf16.h>
#include <cstdint>

#define B_DIM  1024
#define H_DIM  2048
#define KTOT   6144
#define NTOT   8192
#define NCH    96      // data chunks: 0-31 x, 32-63 hi, 64-95 lo(weights pre-scaled 5/256)
#define STAGES 3
#define CHUNK_BYTES 32768            // A 128x64x2 = 16KB + B 128x64x2 = 16KB
#define SMEM_BYTES (STAGES * CHUNK_BYTES)   // 96KB

// h scale: S = 256*127/5; v = round(hx*S) in [-32511,32511]; v = hi*256 + lo
#define SCALE_H 6502.4f
#define VCLAMP  32511.0f

__device__ __align__(256) __nv_bfloat16 g_A[(size_t)B_DIM * KTOT];
__device__ __align__(256) __nv_bfloat16 g_B[(size_t)NTOT * KTOT];
__device__ float g_bias[NTOT];

// ------------------------------- helpers ----------------------------------

__device__ __forceinline__ uint32_t smem_u32(const void* p) {
    uint32_t a;
    asm("{ .reg .u64 t; cvta.to.shared.u64 t, %1; cvt.u32.u64 %0, t; }"
        : "=r"(a) : "l"(p));
    return a;
}

__device__ __forceinline__ float fq8(float v) {
    float q = rintf(v * 127.0f);
    q = fminf(127.0f, fmaxf(-127.0f, q));
    return q * (1.0f / 127.0f);
}

__device__ __forceinline__ float sigm_(float x) {
    return 1.0f / (1.0f + expf(-x));
}

__device__ __forceinline__ float tanh_(float x) {
    float e = expf(-2.0f * fabsf(x));
    return copysignf((1.0f - e) / (1.0f + e), x);
}

__device__ __forceinline__ float q127f(float w) {
    float q = rintf(w * 127.0f);
    return fminf(127.0f, fmaxf(-127.0f, q));
}

// ------------------------------ prep kernels ------------------------------

__global__ void prep_A(const float* __restrict__ x, const float* __restrict__ hx) {
    const int b = blockIdx.y;
    const int c4 = blockIdx.x * 256 + threadIdx.x;      // 0..511
    const int k = c4 << 2;
    const float4 xv = *reinterpret_cast<const float4*>(x + (size_t)b * 2048 + k);
    const float4 hv = *reinterpret_cast<const float4*>(hx + (size_t)b * 2048 + k);
    const float* xf = reinterpret_cast<const float*>(&xv);
    const float* hf = reinterpret_cast<const float*>(&hv);
    ushort4 xq, hiq, loq;
    unsigned short* xp = reinterpret_cast<unsigned short*>(&xq);
    unsigned short* hp = reinterpret_cast<unsigned short*>(&hiq);
    unsigned short* lp = reinterpret_cast<unsigned short*>(&loq);
#pragma unroll
    for (int j = 0; j < 4; ++j) {
        xp[j] = __bfloat16_as_ushort(__float2bfloat16_rn(q127f(xf[j])));
        float vf = rintf(hf[j] * SCALE_H);
        vf = fminf(VCLAMP, fmaxf(-VCLAMP, vf));
        int v = (int)vf;
        int hi = (v + 128) >> 8;            // hi in [-127,127]
        int lo = v - (hi << 8);             // lo in [-128,127]
        hp[j] = __bfloat16_as_ushort(__float2bfloat16_rn((float)hi));
        lp[j] = __bfloat16_as_ushort(__float2bfloat16_rn((float)lo));
    }
    size_t base = (size_t)b * KTOT + k;
    *reinterpret_cast<ushort4*>(g_A + base)        = xq;
    *reinterpret_cast<ushort4*>(g_A + base + 2048) = hiq;
    *reinterpret_cast<ushort4*>(g_A + base + 4096) = loq;
}

// B row r=4u+g from orig row g*2048+u:
//   [0,2048)    wxI               (x region)
//   [2048,4096) whI*5             (hi region)
//   [4096,6144) whI*(5/256)       (lo region; 5/256 exact in bf16)
__global__ void prep_W(const float* __restrict__ wx, const float* __restrict__ wh) {
    const int r = blockIdx.y;
    const int c4 = blockIdx.x * 256 + threadIdx.x;      // 0..1535
    const int u = r >> 2, g = r & 3;
    const size_t orig = (size_t)(g * H_DIM + u) * 2048;
    ushort4 outv;
    unsigned short* op = reinterpret_cast<unsigned short*>(&outv);
    if (c4 < 512) {
        const float4 wv = *reinterpret_cast<const float4*>(wx + orig + (c4 << 2));
        const float* wf = reinterpret_cast<const float*>(&wv);
#pragma unroll
        for (int j = 0; j < 4; ++j)
            op[j] = __bfloat16_as_ushort(__float2bfloat16_rn(q127f(wf[j])));
    } else if (c4 < 1024) {
        const float4 wv = *reinterpret_cast<const float4*>(wh + orig + ((c4 - 512) << 2));
        const float* wf = reinterpret_cast<const float*>(&wv);
#pragma unroll
        for (int j = 0; j < 4; ++j)
            op[j] = __bfloat16_as_ushort(__float2bfloat16_rn(5.0f * q127f(wf[j])));
    } else {
        const float4 wv = *reinterpret_cast<const float4*>(wh + orig + ((c4 - 1024) << 2));
        const float* wf = reinterpret_cast<const float*>(&wv);
#pragma unroll
        for (int j = 0; j < 4; ++j)
            op[j] = __bfloat16_as_ushort(
                __float2bfloat16_rn(0.01953125f * q127f(wf[j])));  // *5/256
    }
    *reinterpret_cast<ushort4*>(g_B + (size_t)r * KTOT + (c4 << 2)) = outv;
}

__global__ void prep_bias(const float* __restrict__ bx, const float* __restrict__ bh) {
    int r = blockIdx.x * 256 + threadIdx.x;
    if (r >= NTOT) return;
    int u = r >> 2, g = r & 3;
    int orig = g * H_DIM + u;
    g_bias[r] = bx[orig] + bh[orig];
}

// ------------------------------- GEMM kernel ------------------------------
// CTA: 128(M) x 128(N), 256 threads, 8 warps (wm=wid>>2 in 0..1, wn=wid&3),
// warp tile 64(M) x 32(N), SINGLE fp32 accumulator, lo chunks processed first.
// 3 stages x 32KB, 2 CTAs/SM -> 16 warps/SM.

__device__ __forceinline__ void prefetch_chunk(uint32_t sb, int stage, int chunk,
                                               int m0, int n0, int tid) {
    const int koff = chunk << 6;        // 64 bf16 per chunk
    const uint32_t sbase = sb + (uint32_t)stage * CHUNK_BYTES;
#pragma unroll
    for (int p = 0; p < 8; ++p) {
        const int idx = p * 256 + tid;      // 0..2047 ; <1024 A, else B
        const bool isA = idx < 1024;
        const int v = idx & 1023;
        const int row = v >> 3;
        const int q = v & 7;
        const uint32_t dst = sbase + (isA ? 0u : 16384u)
                           + (uint32_t)(row << 7)
                           + (uint32_t)((q ^ (row & 7)) << 4);
        const __nv_bfloat16* src = isA
            ? g_A + (size_t)(m0 + row) * KTOT + koff + (q << 3)
            : g_B + (size_t)(n0 + row) * KTOT + koff + (q << 3);
        asm volatile("cp.async.cg.shared.global [%0], [%1], 16;"
                     :: "r"(dst), "l"(src));
    }
}

#define COMPUTE_CHUNK(ACC, SA)                                                 \
  {                                                                            \
    const uint32_t sA = (SA);                                                  \
    const uint32_t sB = sA + 16384u;                                           \
    _Pragma("unroll")                                                          \
    for (int ks = 0; ks < 4; ++ks) {                                           \
      uint32_t a[4][4], b[2][4];                                               \
      _Pragma("unroll")                                                        \
      for (int mf = 0; mf < 4; ++mf) {                                         \
        const int row = wm * 64 + mf * 16 + rsel;                              \
        const uint32_t ad = sA + (uint32_t)(row << 7)                          \
                          + (uint32_t)((((ks * 2 + khalf)) ^ (row & 7)) << 4); \
        asm("ldmatrix.sync.aligned.m8n8.x4.shared.b16 {%0,%1,%2,%3}, [%4];"    \
          : "=r"(a[mf][0]), "=r"(a[mf][1]), "=r"(a[mf][2]), "=r"(a[mf][3])     \
          : "r"(ad) : "memory");                                               \
      }                                                                        \
      _Pragma("unroll")                                                        \
      for (int np = 0; np < 2; ++np) {                                         \
        const int row = wn * 32 + np * 16 + rsel;                              \
        const uint32_t bd = sB + (uint32_t)(row << 7)                          \
                          + (uint32_t)((((ks * 2 + khalf)) ^ (row & 7)) << 4); \
        asm("ldmatrix.sync.aligned.m8n8.x4.shared.b16 {%0,%1,%2,%3}, [%4];"    \
          : "=r"(b[np][0]), "=r"(b[np][1]), "=r"(b[np][2]), "=r"(b[np][3])     \
          : "r"(bd) : "memory");                                               \
      }                                                                        \
      _Pragma("unroll")                                                        \
      for (int mf = 0; mf < 4; ++mf) {                                         \
        _Pragma("unroll")                                                      \
        for (int nf = 0; nf < 4; ++nf) {                                       \
          asm("mma.sync.aligned.m16n8k16.row.col.f32.bf16.bf16.f32 "           \
            "{%0,%1,%2,%3}, {%4,%5,%6,%7}, {%8,%9}, {%0,%1,%2,%3};"            \
            : "+f"(ACC[mf][nf][0]), "+f"(ACC[mf][nf][1]),                      \
              "+f"(ACC[mf][nf][2]), "+f"(ACC[mf][nf][3])                       \
            : "r"(a[mf][0]), "r"(a[mf][1]), "r"(a[mf][2]), "r"(a[mf][3]),      \
              "r"(b[nf >> 1][nf & 1]), "r"(b[nf >> 1][2 + (nf & 1)]));         \
        }                                                                      \
      }                                                                        \
    }                                                                          \
  }

__global__ __launch_bounds__(256, 2)
void lstm_hmma_kernel(const float* __restrict__ cx, float* __restrict__ out) {
    extern __shared__ char smem[];
    const uint32_t sb = smem_u32(smem);
    const int tid = threadIdx.x, lane = tid & 31, wid = tid >> 5;
    const int wm = wid >> 2, wn = wid & 3;     // wm 0..1 (M64), wn 0..3 (N32)
    const int m0 = blockIdx.y << 7, n0 = blockIdx.x << 7;
    const int rsel = lane & 15, khalf = lane >> 4;

    float acc[4][4][4];
#pragma unroll
    for (int i = 0; i < 4; ++i)
#pragma unroll
        for (int j = 0; j < 4; ++j)
#pragma unroll
            for (int k = 0; k < 4; ++k) acc[i][j][k] = 0.0f;

    // chunk processing order: lo (64..95) FIRST, then x+hi (0..63);
    // exact small fractions accumulate before large integers.
    // data_chunk(i) = i<32 ? i+64 : i-32
    prefetch_chunk(sb, 0, 64, m0, n0, tid);
    asm volatile("cp.async.commit_group;");
    prefetch_chunk(sb, 1, 65, m0, n0, tid);
    asm volatile("cp.async.commit_group;");

#pragma unroll 3
    for (int i = 0; i < NCH; ++i) {
        asm volatile("cp.async.wait_group 1;");
        __syncthreads();   // chunk i visible; stage (i+2)%3 reusable
        if (i + 2 < NCH) {
            const int nc = (i + 2 < 32) ? (i + 66) : (i - 30);
            prefetch_chunk(sb, (i + 2) % 3, nc, m0, n0, tid);
        }
        asm volatile("cp.async.commit_group;");   // empty group ok at tail
        COMPUTE_CHUNK(acc, sb + (uint32_t)((i % 3) * CHUNK_BYTES))
    }
    __syncthreads();

    // ---------------- fused LSTM epilogue ----------------
    float* cx_sm = reinterpret_cast<float*>(smem);        // 128 x 33
    float* h_sm = cx_sm + 128 * 33;
    float* c_sm = h_sm + 128 * 33;
    const int u0 = n0 >> 2;                                // 32 units per tile
#pragma unroll
    for (int t = 0; t < 16; ++t) {
        const int idx = t * 256 + tid;
        const int r = idx >> 5, u = idx & 31;
        cx_sm[r * 33 + u] = cx[(size_t)(m0 + r) * H_DIM + u0 + u];
    }
    __syncthreads();

    const float INV = 1.0f / 16129.0f;              // 1/127^2
    const bool oddl = (lane & 1) != 0;
#pragma unroll
    for (int mf = 0; mf < 4; ++mf) {
#pragma unroll
        for (int nf = 0; nf < 4; ++nf) {
            const int col0 = wn * 32 + nf * 8 + 2 * (lane & 3);
            float v0 = fmaf(acc[mf][nf][0], INV, g_bias[n0 + col0]);
            float v1 = fmaf(acc[mf][nf][1], INV, g_bias[n0 + col0 + 1]);
            float v2 = fmaf(acc[mf][nf][2], INV, g_bias[n0 + col0]);
            float v3 = fmaf(acc[mf][nf][3], INV, g_bias[n0 + col0 + 1]);
            float p0 = __shfl_xor_sync(0xFFFFFFFFu, v0, 1);
            float p1 = __shfl_xor_sync(0xFFFFFFFFu, v1, 1);
            float p2 = __shfl_xor_sync(0xFFFFFFFFu, v2, 1);
            float p3 = __shfl_xor_sync(0xFFFFFFFFu, v3, 1);
            const float gf = oddl ? p2 : v0;
            const float gi = oddl ? p3 : v1;
            const float gg = oddl ? v2 : p0;
            const float go = oddl ? v3 : p1;
            const int r = wm * 64 + mf * 16 + (lane >> 2) + (oddl ? 8 : 0);
            const int ul = wn * 8 + nf * 2 + ((lane & 3) >> 1);
            const float f = fq8(sigm_(gf));
            const float ii = fq8(sigm_(gi));
            const float gq = fq8(tanh_(gg));
            const float o = fq8(sigm_(go));
            const float cn = f * cx_sm[r * 33 + ul] + ii * gq;
            h_sm[r * 33 + ul] = o * fq8(tanh_(cn));
            c_sm[r * 33 + ul] = fq8(cn);
        }
    }
    __syncthreads();

    float* hout = out;
    float* cout_ = out + (size_t)B_DIM * H_DIM;
#pragma unroll
    for (int t = 0; t < 16; ++t) {
        const int idx = t * 256 + tid;
        const int r = idx >> 5, u = idx & 31;
        hout[(size_t)(m0 + r) * H_DIM + u0 + u] = h_sm[r * 33 + u];
        cout_[(size_t)(m0 + r) * H_DIM + u0 + u] = c_sm[r * 33 + u];
    }
}

// ------------------------------- launcher ---------------------------------

extern "C" void kernel_launch(void* const* d_in, const int* in_sizes, int n_in,
                              void* d_out, int out_size) {
    (void)in_sizes; (void)n_in; (void)out_size;
    const float* x  = (const float*)d_in[0];
    const float* hx = (const float*)d_in[1];
    const float* cx = (const float*)d_in[2];
    const float* wx = (const float*)d_in[3];
    const float* bx = (const float*)d_in[4];
    const float* wh = (const float*)d_in[5];
    const float* bh = (const float*)d_in[6];
    float* out = (float*)d_out;

    cudaFuncSetAttribute(lstm_hmma_kernel,
                         cudaFuncAttributeMaxDynamicSharedMemorySize, SMEM_BYTES);

    prep_A<<<dim3(2, B_DIM), 256>>>(x, hx);
    prep_W<<<dim3(6, NTOT), 256>>>(wx, wh);
    prep_bias<<<NTOT / 256, 256>>>(bx, bh);

    dim3 grid(NTOT / 128, B_DIM / 128);         // 64 x 8 = 512 CTAs
    lstm_hmma_kernel<<<grid, 256, SMEM_BYTES>>>(cx, out);
}

// round 17
// speedup vs baseline: 1.0113x; 1.0113x over previous
#include <cuda_runtime.h>
#include <cuda_bf16.h>
#include <cstdint>

#define B_DIM  1024
#define H_DIM  2048
#define KTOT   6144
#define NTOT   8192
#define NCH    96      // data chunks: 0-31 x, 32-63 hi, 64-95 lo(weights pre-scaled 5/256)
#define STAGES 3
#define CHUNK_BYTES 32768            // A 128x64x2 = 16KB + B 128x64x2 = 16KB
#define SMEM_BYTES (STAGES * CHUNK_BYTES)   // 96KB

// h scale: S = 256*127/5; v = round(hx*S) in [-32511,32511]; v = hi*256 + lo
#define SCALE_H 6502.4f
#define VCLAMP  32511.0f

__device__ __align__(256) __nv_bfloat16 g_A[(size_t)B_DIM * KTOT];
__device__ __align__(256) __nv_bfloat16 g_B[(size_t)NTOT * KTOT];
__device__ float g_bias[NTOT];

// ------------------------------- helpers ----------------------------------

__device__ __forceinline__ uint32_t smem_u32(const void* p) {
    uint32_t a;
    asm("{ .reg .u64 t; cvta.to.shared.u64 t, %1; cvt.u32.u64 %0, t; }"
        : "=r"(a) : "l"(p));
    return a;
}

__device__ __forceinline__ float fq8(float v) {
    float q = rintf(v * 127.0f);
    q = fminf(127.0f, fmaxf(-127.0f, q));
    return q * (1.0f / 127.0f);
}

__device__ __forceinline__ float sigm_(float x) {
    return 1.0f / (1.0f + expf(-x));
}

__device__ __forceinline__ float tanh_(float x) {
    float e = expf(-2.0f * fabsf(x));
    return copysignf((1.0f - e) / (1.0f + e), x);
}

__device__ __forceinline__ float q127f(float w) {
    float q = rintf(w * 127.0f);
    return fminf(127.0f, fmaxf(-127.0f, q));
}

// ------------------------------ prep kernels ------------------------------

__global__ void prep_A(const float* __restrict__ x, const float* __restrict__ hx) {
    const int b = blockIdx.y;
    const int c4 = blockIdx.x * 256 + threadIdx.x;      // 0..511
    const int k = c4 << 2;
    const float4 xv = *reinterpret_cast<const float4*>(x + (size_t)b * 2048 + k);
    const float4 hv = *reinterpret_cast<const float4*>(hx + (size_t)b * 2048 + k);
    const float* xf = reinterpret_cast<const float*>(&xv);
    const float* hf = reinterpret_cast<const float*>(&hv);
    ushort4 xq, hiq, loq;
    unsigned short* xp = reinterpret_cast<unsigned short*>(&xq);
    unsigned short* hp = reinterpret_cast<unsigned short*>(&hiq);
    unsigned short* lp = reinterpret_cast<unsigned short*>(&loq);
#pragma unroll
    for (int j = 0; j < 4; ++j) {
        xp[j] = __bfloat16_as_ushort(__float2bfloat16_rn(q127f(xf[j])));
        float vf = rintf(hf[j] * SCALE_H);
        vf = fminf(VCLAMP, fmaxf(-VCLAMP, vf));
        int v = (int)vf;
        int hi = (v + 128) >> 8;            // hi in [-127,127]
        int lo = v - (hi << 8);             // lo in [-128,127]
        hp[j] = __bfloat16_as_ushort(__float2bfloat16_rn((float)hi));
        lp[j] = __bfloat16_as_ushort(__float2bfloat16_rn((float)lo));
    }
    size_t base = (size_t)b * KTOT + k;
    *reinterpret_cast<ushort4*>(g_A + base)        = xq;
    *reinterpret_cast<ushort4*>(g_A + base + 2048) = hiq;
    *reinterpret_cast<ushort4*>(g_A + base + 4096) = loq;
}

// B row r=4u+g from orig row g*2048+u:
//   [0,2048)    wxI               (x region)
//   [2048,4096) whI*5             (hi region)
//   [4096,6144) whI*(5/256)       (lo region; 5/256 exact in bf16)
__global__ void prep_W(const float* __restrict__ wx, const float* __restrict__ wh) {
    const int r = blockIdx.y;
    const int c4 = blockIdx.x * 256 + threadIdx.x;      // 0..1535
    const int u = r >> 2, g = r & 3;
    const size_t orig = (size_t)(g * H_DIM + u) * 2048;
    ushort4 outv;
    unsigned short* op = reinterpret_cast<unsigned short*>(&outv);
    if (c4 < 512) {
        const float4 wv = *reinterpret_cast<const float4*>(wx + orig + (c4 << 2));
        const float* wf = reinterpret_cast<const float*>(&wv);
#pragma unroll
        for (int j = 0; j < 4; ++j)
            op[j] = __bfloat16_as_ushort(__float2bfloat16_rn(q127f(wf[j])));
    } else if (c4 < 1024) {
        const float4 wv = *reinterpret_cast<const float4*>(wh + orig + ((c4 - 512) << 2));
        const float* wf = reinterpret_cast<const float*>(&wv);
#pragma unroll
        for (int j = 0; j < 4; ++j)
            op[j] = __bfloat16_as_ushort(__float2bfloat16_rn(5.0f * q127f(wf[j])));
    } else {
        const float4 wv = *reinterpret_cast<const float4*>(wh + orig + ((c4 - 1024) << 2));
        const float* wf = reinterpret_cast<const float*>(&wv);
#pragma unroll
        for (int j = 0; j < 4; ++j)
            op[j] = __bfloat16_as_ushort(
                __float2bfloat16_rn(0.01953125f * q127f(wf[j])));  // *5/256
    }
    *reinterpret_cast<ushort4*>(g_B + (size_t)r * KTOT + (c4 << 2)) = outv;
}

__global__ void prep_bias(const float* __restrict__ bx, const float* __restrict__ bh) {
    int r = blockIdx.x * 256 + threadIdx.x;
    if (r >= NTOT) return;
    int u = r >> 2, g = r & 3;
    int orig = g * H_DIM + u;
    g_bias[r] = bx[orig] + bh[orig];
}

// ------------------------------- GEMM kernel ------------------------------
// CTA: 128(M) x 128(N), 256 threads, 8 warps (wm in 0..1 M64, wn in 0..3 N32),
// warp tile 64(M) x 32(N), single fp32 accumulator, lo chunks first.
// Register-lean compute order: per ks load B frags, then per mf one A-ldsm
// immediately consumed by its 4 HMMAs (live A frags = 4 regs, no spill).

__device__ __forceinline__ void prefetch_chunk(uint32_t sb, int stage, int chunk,
                                               int m0, int n0, int tid) {
    const int koff = chunk << 6;        // 64 bf16 per chunk
    const uint32_t sbase = sb + (uint32_t)stage * CHUNK_BYTES;
#pragma unroll
    for (int p = 0; p < 8; ++p) {
        const int idx = p * 256 + tid;      // 0..2047 ; <1024 A, else B
        const bool isA = idx < 1024;
        const int v = idx & 1023;
        const int row = v >> 3;
        const int q = v & 7;
        const uint32_t dst = sbase + (isA ? 0u : 16384u)
                           + (uint32_t)(row << 7)
                           + (uint32_t)((q ^ (row & 7)) << 4);
        const __nv_bfloat16* src = isA
            ? g_A + (size_t)(m0 + row) * KTOT + koff + (q << 3)
            : g_B + (size_t)(n0 + row) * KTOT + koff + (q << 3);
        asm volatile("cp.async.cg.shared.global [%0], [%1], 16;"
                     :: "r"(dst), "l"(src));
    }
}

#define COMPUTE_CHUNK(ACC, SA)                                                 \
  {                                                                            \
    const uint32_t sA = (SA);                                                  \
    const uint32_t sB = sA + 16384u;                                           \
    _Pragma("unroll")                                                          \
    for (int ks = 0; ks < 4; ++ks) {                                           \
      uint32_t b[2][4];                                                        \
      _Pragma("unroll")                                                        \
      for (int np = 0; np < 2; ++np) {                                         \
        const int row = wn * 32 + np * 16 + rsel;                              \
        const uint32_t bd = sB + (uint32_t)(row << 7)                          \
                          + (uint32_t)((((ks * 2 + khalf)) ^ (row & 7)) << 4); \
        asm("ldmatrix.sync.aligned.m8n8.x4.shared.b16 {%0,%1,%2,%3}, [%4];"    \
          : "=r"(b[np][0]), "=r"(b[np][1]), "=r"(b[np][2]), "=r"(b[np][3])     \
          : "r"(bd) : "memory");                                               \
      }                                                                        \
      _Pragma("unroll")                                                        \
      for (int mf = 0; mf < 4; ++mf) {                                         \
        uint32_t a[4];                                                         \
        const int row = wm * 64 + mf * 16 + rsel;                              \
        const uint32_t ad = sA + (uint32_t)(row << 7)                          \
                          + (uint32_t)((((ks * 2 + khalf)) ^ (row & 7)) << 4); \
        asm("ldmatrix.sync.aligned.m8n8.x4.shared.b16 {%0,%1,%2,%3}, [%4];"    \
          : "=r"(a[0]), "=r"(a[1]), "=r"(a[2]), "=r"(a[3])                     \
          : "r"(ad) : "memory");                                               \
        _Pragma("unroll")                                                      \
        for (int nf = 0; nf < 4; ++nf) {                                       \
          asm("mma.sync.aligned.m16n8k16.row.col.f32.bf16.bf16.f32 "           \
            "{%0,%1,%2,%3}, {%4,%5,%6,%7}, {%8,%9}, {%0,%1,%2,%3};"            \
            : "+f"(ACC[mf][nf][0]), "+f"(ACC[mf][nf][1]),                      \
              "+f"(ACC[mf][nf][2]), "+f"(ACC[mf][nf][3])                       \
            : "r"(a[0]), "r"(a[1]), "r"(a[2]), "r"(a[3]),                      \
              "r"(b[nf >> 1][nf & 1]), "r"(b[nf >> 1][2 + (nf & 1)]));         \
        }                                                                      \
      }                                                                        \
    }                                                                          \
  }

__global__ __launch_bounds__(256, 2)
void lstm_hmma_kernel(const float* __restrict__ cx, float* __restrict__ out) {
    extern __shared__ char smem[];
    const uint32_t sb = smem_u32(smem);
    const int tid = threadIdx.x, lane = tid & 31, wid = tid >> 5;
    const int wm = wid >> 2, wn = wid & 3;     // wm 0..1 (M64), wn 0..3 (N32)
    const int m0 = blockIdx.y << 7, n0 = blockIdx.x << 7;
    const int rsel = lane & 15, khalf = lane >> 4;

    float acc[4][4][4];
#pragma unroll
    for (int i = 0; i < 4; ++i)
#pragma unroll
        for (int j = 0; j < 4; ++j)
#pragma unroll
            for (int k = 0; k < 4; ++k) acc[i][j][k] = 0.0f;

    // chunk processing order: lo (64..95) FIRST, then x+hi (0..63).
    prefetch_chunk(sb, 0, 64, m0, n0, tid);
    asm volatile("cp.async.commit_group;");
    prefetch_chunk(sb, 1, 65, m0, n0, tid);
    asm volatile("cp.async.commit_group;");

#pragma unroll 3
    for (int i = 0; i < NCH; ++i) {
        asm volatile("cp.async.wait_group 1;");
        __syncthreads();   // chunk i visible; stage (i+2)%3 reusable
        if (i + 2 < NCH) {
            const int nc = (i + 2 < 32) ? (i + 66) : (i - 30);
            prefetch_chunk(sb, (i + 2) % 3, nc, m0, n0, tid);
        }
        asm volatile("cp.async.commit_group;");   // empty group ok at tail
        COMPUTE_CHUNK(acc, sb + (uint32_t)((i % 3) * CHUNK_BYTES))
    }
    __syncthreads();

    // ---------------- fused LSTM epilogue ----------------
    float* cx_sm = reinterpret_cast<float*>(smem);        // 128 x 33
    float* h_sm = cx_sm + 128 * 33;
    float* c_sm = h_sm + 128 * 33;
    const int u0 = n0 >> 2;                                // 32 units per tile
#pragma unroll
    for (int t = 0; t < 16; ++t) {
        const int idx = t * 256 + tid;
        const int r = idx >> 5, u = idx & 31;
        cx_sm[r * 33 + u] = cx[(size_t)(m0 + r) * H_DIM + u0 + u];
    }
    __syncthreads();

    const float INV = 1.0f / 16129.0f;              // 1/127^2
    const bool oddl = (lane & 1) != 0;
#pragma unroll
    for (int mf = 0; mf < 4; ++mf) {
#pragma unroll
        for (int nf = 0; nf < 4; ++nf) {
            const int col0 = wn * 32 + nf * 8 + 2 * (lane & 3);
            float v0 = fmaf(acc[mf][nf][0], INV, g_bias[n0 + col0]);
            float v1 = fmaf(acc[mf][nf][1], INV, g_bias[n0 + col0 + 1]);
            float v2 = fmaf(acc[mf][nf][2], INV, g_bias[n0 + col0]);
            float v3 = fmaf(acc[mf][nf][3], INV, g_bias[n0 + col0 + 1]);
            float p0 = __shfl_xor_sync(0xFFFFFFFFu, v0, 1);
            float p1 = __shfl_xor_sync(0xFFFFFFFFu, v1, 1);
            float p2 = __shfl_xor_sync(0xFFFFFFFFu, v2, 1);
            float p3 = __shfl_xor_sync(0xFFFFFFFFu, v3, 1);
            const float gf = oddl ? p2 : v0;
            const float gi = oddl ? p3 : v1;
            const float gg = oddl ? v2 : p0;
            const float go = oddl ? v3 : p1;
            const int r = wm * 64 + mf * 16 + (lane >> 2) + (oddl ? 8 : 0);
            const int ul = wn * 8 + nf * 2 + ((lane & 3) >> 1);
            const float f = fq8(sigm_(gf));
            const float ii = fq8(sigm_(gi));
            const float gq = fq8(tanh_(gg));
            const float o = fq8(sigm_(go));
            const float cn = f * cx_sm[r * 33 + ul] + ii * gq;
            h_sm[r * 33 + ul] = o * fq8(tanh_(cn));
            c_sm[r * 33 + ul] = fq8(cn);
        }
    }
    __syncthreads();

    float* hout = out;
    float* cout_ = out + (size_t)B_DIM * H_DIM;
#pragma unroll
    for (int t = 0; t < 16; ++t) {
        const int idx = t * 256 + tid;
        const int r = idx >> 5, u = idx & 31;
        hout[(size_t)(m0 + r) * H_DIM + u0 + u] = h_sm[r * 33 + u];
        cout_[(size_t)(m0 + r) * H_DIM + u0 + u] = c_sm[r * 33 + u];
    }
}

// ------------------------------- launcher ---------------------------------

extern "C" void kernel_launch(void* const* d_in, const int* in_sizes, int n_in,
                              void* d_out, int out_size) {
    (void)in_sizes; (void)n_in; (void)out_size;
    const float* x  = (const float*)d_in[0];
    const float* hx = (const float*)d_in[1];
    const float* cx = (const float*)d_in[2];
    const float* wx = (const float*)d_in[3];
    const float* bx = (const float*)d_in[4];
    const float* wh = (const float*)d_in[5];
    const float* bh = (const float*)d_in[6];
    float* out = (float*)d_out;

    cudaFuncSetAttribute(lstm_hmma_kernel,
                         cudaFuncAttributeMaxDynamicSharedMemorySize, SMEM_BYTES);

    prep_A<<<dim3(2, B_DIM), 256>>>(x, hx);
    prep_W<<<dim3(6, NTOT), 256>>>(wx, wh);
    prep_bias<<<NTOT / 256, 256>>>(bx, bh);

    dim3 grid(NTOT / 128, B_DIM / 128);         // 64 x 8 = 512 CTAs
    lstm_hmma_kernel<<<grid, 256, SMEM_BYTES>>>(cx, out);
}